// round 3
// baseline (speedup 1.0000x reference)
#include <cuda_runtime.h>

// Problem constants
#define NB  4
#define NT  1024
#define ND  1024
#define NH  16
#define NHD 64

// ---------------------------------------------------------------------------
// Scratch (alloc-free: __device__ globals)
// ---------------------------------------------------------------------------
static __device__ float g_K [(size_t)NB * NT * ND];            // 16 MB
static __device__ float g_Q [(size_t)NB * NT * ND];            // 16 MB
static __device__ float g_V [(size_t)NB * NT * ND];            // 16 MB
static __device__ float g_AO[(size_t)NB * NT * ND];            // 16 MB
static __device__ float g_S [(size_t)NB * NH * NT * NT];       // 256 MB  [b,h,k,q]

// ---------------------------------------------------------------------------
// Generic NT GEMM with bias:  C[m,n] = sum_k A[m,k]*B[n,k] + bias[n]
// Tiles: 64x64, K-step 16, 256 threads, 4x4 per thread.
// M,N multiples of 64; K multiple of 16 (true for all uses here).
// ---------------------------------------------------------------------------
__global__ __launch_bounds__(256) void gemm_nt_bias_k(
    const float* __restrict__ A, int lda,
    const float* __restrict__ Bm, int ldb,
    const float* __restrict__ bias,
    float* __restrict__ C, int ldc, int K)
{
    __shared__ float As[16][65];
    __shared__ float Bs[16][65];
    const int m0 = blockIdx.y * 64, n0 = blockIdx.x * 64;
    const int tid = threadIdx.x;
    const int tx = tid & 15, ty = tid >> 4;
    float acc[4][4] = {};

    for (int k0 = 0; k0 < K; k0 += 16) {
        #pragma unroll
        for (int i = tid; i < 1024; i += 256) {
            const int r = i >> 4, kk = i & 15;
            As[kk][r] = A [(size_t)(m0 + r) * lda + k0 + kk];
            Bs[kk][r] = Bm[(size_t)(n0 + r) * ldb + k0 + kk];
        }
        __syncthreads();
        #pragma unroll
        for (int kk = 0; kk < 16; kk++) {
            float a[4], b[4];
            #pragma unroll
            for (int i = 0; i < 4; i++) a[i] = As[kk][ty * 4 + i];
            #pragma unroll
            for (int j = 0; j < 4; j++) b[j] = Bs[kk][tx * 4 + j];
            #pragma unroll
            for (int i = 0; i < 4; i++)
                #pragma unroll
                for (int j = 0; j < 4; j++)
                    acc[i][j] += a[i] * b[j];
        }
        __syncthreads();
    }

    #pragma unroll
    for (int i = 0; i < 4; i++) {
        const int gm = m0 + ty * 4 + i;
        #pragma unroll
        for (int j = 0; j < 4; j++) {
            const int gn = n0 + tx * 4 + j;
            float v = acc[i][j];
            if (bias) v += bias[gn];
            C[(size_t)gm * ldc + gn] = v;
        }
    }
}

// ---------------------------------------------------------------------------
// scores[b,h,k,q] = (q>k) ? -1e30 : dot(K[b,k,h,:], Q[b,q,h,:]) / 32
// NT GEMM per (b,h), K=64.  Fully-masked tiles (q0 > k0+63) skipped entirely;
// softmax never reads them.
// ---------------------------------------------------------------------------
__global__ __launch_bounds__(256) void scores_k()
{
    const int z = blockIdx.z, b = z >> 4, h = z & 15;
    const int m0 = blockIdx.y * 64, n0 = blockIdx.x * 64;   // m = k-index, n = q-index
    if (n0 > m0 + 63) return;                               // fully masked tile

    const float* __restrict__ A  = g_K + (size_t)b * NT * ND + h * NHD;
    const float* __restrict__ Bm = g_Q + (size_t)b * NT * ND + h * NHD;
    float* __restrict__ C = g_S + (size_t)z * NT * NT;

    __shared__ float As[16][65];
    __shared__ float Bs[16][65];
    const int tid = threadIdx.x;
    const int tx = tid & 15, ty = tid >> 4;
    float acc[4][4] = {};

    #pragma unroll
    for (int k0 = 0; k0 < NHD; k0 += 16) {
        #pragma unroll
        for (int i = tid; i < 1024; i += 256) {
            const int r = i >> 4, kk = i & 15;
            As[kk][r] = A [(size_t)(m0 + r) * ND + k0 + kk];
            Bs[kk][r] = Bm[(size_t)(n0 + r) * ND + k0 + kk];
        }
        __syncthreads();
        #pragma unroll
        for (int kk = 0; kk < 16; kk++) {
            float a[4], b2[4];
            #pragma unroll
            for (int i = 0; i < 4; i++) a[i] = As[kk][ty * 4 + i];
            #pragma unroll
            for (int j = 0; j < 4; j++) b2[j] = Bs[kk][tx * 4 + j];
            #pragma unroll
            for (int i = 0; i < 4; i++)
                #pragma unroll
                for (int j = 0; j < 4; j++)
                    acc[i][j] += a[i] * b2[j];
        }
        __syncthreads();
    }

    #pragma unroll
    for (int i = 0; i < 4; i++) {
        const int gm = m0 + ty * 4 + i;
        #pragma unroll
        for (int j = 0; j < 4; j++) {
            const int gn = n0 + tx * 4 + j;
            const float v = (gn > gm) ? -1e30f : acc[i][j] * 0.03125f;  // 1/sqrt(1024)
            C[(size_t)gm * NT + gn] = v;
        }
    }
}

// ---------------------------------------------------------------------------
// Softmax over q for one (b,k) row-group (all 16 heads at once).
//  - reads scores only for q<=k
//  - writes weights output in bkqh layout (fully coalesced via SMEM transpose)
//  - writes normalized weights back to g_S (bhkq) for q < ceil64(k+1)
//    (zeros in the diagonal-tile masked region, needed by the AV GEMM)
// dynamic smem: 16 * 1025 * 4 = 65600 bytes
// ---------------------------------------------------------------------------
__global__ __launch_bounds__(256) void softmax_k(float* __restrict__ outW, int write_w)
{
    extern __shared__ float sh[];           // [16][1025]
    __shared__ float s_inv[16];

    const int bk = blockIdx.x;
    const int b = bk >> 10, kidx = bk & 1023;
    const int tid = threadIdx.x;
    const size_t sbase = (size_t)b * NH * NT * NT + (size_t)kidx * NT;

    // Load scaled+masked scores into SMEM (fillers for q>kidx)
    for (int i = tid; i < NH * NT; i += 256) {
        const int h = i >> 10, q = i & 1023;
        float v = -1e30f;
        if (q <= kidx) v = g_S[sbase + (size_t)h * NT * NT + q];
        sh[h * 1025 + q] = v;
    }
    __syncthreads();

    // Per-head max + expsum (8 warps, 2 heads each)
    const int warp = tid >> 5, lane = tid & 31;
    for (int h = warp; h < NH; h += 8) {
        float m = -1e30f;
        for (int q = lane; q < NT; q += 32) m = fmaxf(m, sh[h * 1025 + q]);
        #pragma unroll
        for (int o = 16; o; o >>= 1) m = fmaxf(m, __shfl_xor_sync(0xffffffffu, m, o));
        float s = 0.f;
        for (int q = lane; q < NT; q += 32) {
            const float e = __expf(sh[h * 1025 + q] - m);
            sh[h * 1025 + q] = e;
            s += e;
        }
        #pragma unroll
        for (int o = 16; o; o >>= 1) s += __shfl_xor_sync(0xffffffffu, s, o);
        if (lane == 0) s_inv[h] = 1.0f / s;
    }
    __syncthreads();

    // Coalesced bkqh weights output (full row incl. exact zeros for q>kidx)
    if (write_w) {
        float* __restrict__ W = outW + (size_t)bk * NT * NH;
        for (int i = tid; i < NT * NH; i += 256) {
            const int q = i >> 4, h = i & 15;
            W[i] = (q <= kidx) ? sh[h * 1025 + q] * s_inv[h] : 0.f;
        }
    }

    // Write normalized weights back to g_S for the AV GEMM (only up to the
    // 64-aligned diagonal boundary; zeros in the masked part of that tile)
    const int qlimit = ((kidx >> 6) + 1) << 6;
    for (int h = 0; h < NH; h++) {
        const float inv = s_inv[h];
        float* __restrict__ dst = &g_S[sbase + (size_t)h * NT * NT];
        for (int q = tid; q < qlimit; q += 256)
            dst[q] = (q <= kidx) ? sh[h * 1025 + q] * inv : 0.f;
    }
}

// ---------------------------------------------------------------------------
// AV: AttnOut[b,k,h,:] = sum_q W[b,h,k,q] * V[b,q,h,:]
// NN GEMM per (b,h): A = W (lda=T), B = V (ldb=D, N contiguous), M=T, N=64.
// K-loop truncated at the causal diagonal (weights beyond are zero anyway).
// ---------------------------------------------------------------------------
__global__ __launch_bounds__(256) void av_k()
{
    const int z = blockIdx.z, b = z >> 4, h = z & 15;
    const int m0 = blockIdx.y * 64;
    const float* __restrict__ A  = g_S + (size_t)z * NT * NT;
    const float* __restrict__ Bm = g_V + (size_t)b * NT * ND + h * NHD;
    float* __restrict__ C = g_AO + (size_t)b * NT * ND + h * NHD;

    __shared__ float As[16][65];
    __shared__ float Bs[16][65];
    const int tid = threadIdx.x;
    const int tx = tid & 15, ty = tid >> 4;
    float acc[4][4] = {};

    const int Kend = m0 + 64;                 // causal truncation
    for (int k0 = 0; k0 < Kend; k0 += 16) {
        #pragma unroll
        for (int i = tid; i < 1024; i += 256) {
            const int r = i >> 4, kk = i & 15;
            As[kk][r] = A[(size_t)(m0 + r) * NT + k0 + kk];
        }
        #pragma unroll
        for (int i = tid; i < 1024; i += 256) {
            const int kk = i >> 6, n = i & 63;
            Bs[kk][n] = Bm[(size_t)(k0 + kk) * ND + n];
        }
        __syncthreads();
        #pragma unroll
        for (int kk = 0; kk < 16; kk++) {
            float a[4], b2[4];
            #pragma unroll
            for (int i = 0; i < 4; i++) a[i] = As[kk][ty * 4 + i];
            #pragma unroll
            for (int j = 0; j < 4; j++) b2[j] = Bs[kk][tx * 4 + j];
            #pragma unroll
            for (int i = 0; i < 4; i++)
                #pragma unroll
                for (int j = 0; j < 4; j++)
                    acc[i][j] += a[i] * b2[j];
        }
        __syncthreads();
    }

    #pragma unroll
    for (int i = 0; i < 4; i++) {
        const int gm = m0 + ty * 4 + i;
        #pragma unroll
        for (int j = 0; j < 4; j++)
            C[(size_t)gm * ND + tx * 4 + j] = acc[i][j];
    }
}

// ---------------------------------------------------------------------------
// Launch
// ---------------------------------------------------------------------------
extern "C" void kernel_launch(void* const* d_in, const int* in_sizes, int n_in,
                              void* d_out, int out_size)
{
    const float* x   = (const float*)d_in[0];
    // d_in[1], d_in[2] (x1, x2) unused; d_in[3] attn_mask is a fixed causal
    // triu mask reproduced analytically in-kernel.
    const float* Wk_ = (const float*)d_in[4];
    const float* bk_ = (const float*)d_in[5];
    const float* Wq_ = (const float*)d_in[6];
    const float* bq_ = (const float*)d_in[7];
    const float* Wv_ = (const float*)d_in[8];
    const float* bv_ = (const float*)d_in[9];
    const float* Wp_ = (const float*)d_in[10];
    const float* bp_ = (const float*)d_in[11];

    float* out  = (float*)d_out;
    const size_t out_elems  = (size_t)NB * NT * ND;             // 4,194,304
    const size_t w_elems    = (size_t)NB * NT * NT * NH;        // 67,108,864
    const int write_w = ((size_t)out_size >= out_elems + w_elems) ? 1 : 0;
    float* outW = out + out_elems;

    float *pK, *pQ, *pV, *pAO;
    cudaGetSymbolAddress((void**)&pK,  g_K);
    cudaGetSymbolAddress((void**)&pQ,  g_Q);
    cudaGetSymbolAddress((void**)&pV,  g_V);
    cudaGetSymbolAddress((void**)&pAO, g_AO);

    cudaFuncSetAttribute(softmax_k, cudaFuncAttributeMaxDynamicSharedMemorySize, 65600);

    const dim3 blk(256);
    const dim3 gProj(ND / 64, (NB * NT) / 64);        // (16, 64)

    // QKV projections (k/q/v = x @ W.T + b)
    gemm_nt_bias_k<<<gProj, blk>>>(x, ND, Wk_, ND, bk_, pK, ND, ND);
    gemm_nt_bias_k<<<gProj, blk>>>(x, ND, Wq_, ND, bq_, pQ, ND, ND);
    gemm_nt_bias_k<<<gProj, blk>>>(x, ND, Wv_, ND, bv_, pV, ND, ND);

    // scores (masked + scaled), per (b,h)
    scores_k<<<dim3(NT / 64, NT / 64, NB * NH), blk>>>();

    // softmax over q + weights output
    softmax_k<<<NB * NT, blk, 65600>>>(outW, write_w);

    // AV
    av_k<<<dim3(1, NT / 64, NB * NH), blk>>>();

    // output projection
    gemm_nt_bias_k<<<gProj, blk>>>(pAO, ND, Wp_, ND, bp_, out, ND, ND);
}